// round 12
// baseline (speedup 1.0000x reference)
#include <cuda_runtime.h>
#include <cuda_fp16.h>
#include <cstdint>

// TpsGridGen: theta (64,50) -> grid (64,256,192,2) fp32
// R12: tensor-pipe rewrite via mma.sync.m16n8k8 (compute_80 PTX -> works
// through the harness's compute_103 lowering; tcgen05 does not).
//   out[px][n] = U[px][k] * C[n][k], n = 2*batch+axis, K=28 pad 32.
//   fp16 hi/lo split, 3 passes (hi*hi + hi*lo + lo*hi), fp32 accum.
//   Block: 64 px x 16-batch group. Warp: 16 px x 32 n. 48 HMMA/warp.

#define OUT_H 256
#define OUT_W 192
#define NPX   (OUT_H * OUT_W)
#define NCP   25
#define NK    28
#define GRP_NB 16     // batches per block
#define PXB    64     // pixels per block

__host__ __device__ constexpr float cpx(int n) { return 0.5f * (float)(n / 5) - 1.0f; }
__host__ __device__ constexpr float cpy(int n) { return 0.5f * (float)(n % 5) - 1.0f; }

// ---------------------------------------------------------------------------
// Compile-time inv(L), transposed to [m][k], RBF rows (k<25) pre-scaled by ln2
// so U can use lg2. (constexpr fp64 Gauss-Jordan w/ pivoting + constexpr log)
// ---------------------------------------------------------------------------
constexpr double cfabs(double x) { return x < 0.0 ? -x : x; }

constexpr double clog(double x) {
    int e = 0;
    while (x >= 1.4142135623730951) { x *= 0.5; e++; }
    while (x <  0.7071067811865476) { x *= 2.0; e--; }
    double t = (x - 1.0) / (x + 1.0), t2 = t * t, p = t, s = 0.0;
    for (int k = 0; k < 27; k++) { s += p / (double)(2 * k + 1); p *= t2; }
    return 2.0 * s + (double)e * 0.6931471805599453094172321214581766;
}

struct alignas(16) TPSLiS { float v[NCP][NK]; };   // [m][k]

constexpr TPSLiS make_lis() {
    const double ax[5] = {-1.0, -0.5, 0.0, 0.5, 1.0};
    double PX[NCP] = {}, PY[NCP] = {};
    for (int i = 0; i < 5; i++)
        for (int j = 0; j < 5; j++) { PX[i*5+j] = ax[i]; PY[i*5+j] = ax[j]; }

    double a[28][56] = {};
    for (int i = 0; i < 25; i++)
        for (int j = 0; j < 25; j++)
            if (i != j) {
                double dx = PX[i]-PX[j], dy = PY[i]-PY[j];
                double d2 = dx*dx + dy*dy;
                a[i][j] = d2 * clog(d2);
            }
    for (int i = 0; i < 25; i++) {
        a[i][25] = 1.0; a[i][26] = PX[i]; a[i][27] = PY[i];
        a[25][i] = 1.0; a[26][i] = PX[i]; a[27][i] = PY[i];
    }
    for (int i = 0; i < 28; i++) a[i][28+i] = 1.0;

    for (int k = 0; k < 28; k++) {
        int piv = k; double best = cfabs(a[k][k]);
        for (int i = k+1; i < 28; i++) {
            double v = cfabs(a[i][k]);
            if (v > best) { best = v; piv = i; }
        }
        if (piv != k)
            for (int j = 0; j < 56; j++) {
                double t = a[k][j]; a[k][j] = a[piv][j]; a[piv][j] = t;
            }
        double inv = 1.0 / a[k][k];
        for (int j = 0; j < 56; j++) a[k][j] *= inv;
        for (int i = 0; i < 28; i++) {
            if (i == k) continue;
            double f = a[i][k];
            if (f != 0.0)
                for (int j = 0; j < 56; j++) a[i][j] -= f * a[k][j];
        }
    }
    const double LN2 = 0.6931471805599453094172321214581766;
    TPSLiS r{};
    for (int m = 0; m < NCP; m++)
        for (int k = 0; k < NK; k++)
            r.v[m][k] = (float)(((k < 25) ? LN2 : 1.0) * a[k][28 + m]);
    return r;
}

__device__ const TPSLiS g_lis = make_lis();

// Compile-time linspace tables (numpy fp64 semantics, endpoint exact).
struct alignas(16) GridTab { float g[448]; };   // [0..191]=gx, [192..447]=gy

constexpr GridTab make_grid() {
    GridTab r{};
    for (int w = 0; w < OUT_W; w++)
        r.g[w] = (float)(-1.0 + (double)w * (2.0 / (double)(OUT_W - 1)));
    r.g[OUT_W - 1] = 1.0f;
    for (int h = 0; h < OUT_H; h++)
        r.g[192 + h] = (float)(-1.0 + (double)h * (2.0 / (double)(OUT_H - 1)));
    r.g[192 + OUT_H - 1] = 1.0f;
    return r;
}

__device__ const GridTab g_grid = make_grid();

// ---------------------------------------------------------------------------
__device__ __forceinline__ uint32_t h2bits(__half2 h) {
    return *reinterpret_cast<uint32_t*>(&h);
}

// Split v0,v1 into fp16 hi pair + fp16 residual pair.
__device__ __forceinline__ void hilo(float v0, float v1, uint32_t& hi, uint32_t& lo) {
    __half2 h = __floats2half2_rn(v0, v1);       // low = v0, high = v1
    float r0 = v0 - __low2float(h);
    float r1 = v1 - __high2float(h);
    hi = h2bits(h);
    lo = h2bits(__floats2half2_rn(r0, r1));
}

__device__ __forceinline__ void mma16n8k8(float& d0, float& d1, float& d2, float& d3,
                                          uint32_t a0, uint32_t a1, uint32_t b0) {
    asm("mma.sync.aligned.m16n8k8.row.col.f32.f16.f16.f32 "
        "{%0,%1,%2,%3},{%4,%5},{%6},{%0,%1,%2,%3};"
        : "+f"(d0), "+f"(d1), "+f"(d2), "+f"(d3)
        : "r"(a0), "r"(a1), "r"(b0));
}

// ---------------------------------------------------------------------------
// Kernel. grid (768, 4), block 128. Block = 64 px x 16 batches (32 n-rows).
// ---------------------------------------------------------------------------
__global__ __launch_bounds__(128) void tps_mma_kernel(
    const float* __restrict__ theta, float2* __restrict__ out) {

    __shared__ __align__(16) float    s_theta[GRP_NB * 50];   // 3.2 KB
    __shared__ __align__(16) float    s_li[NCP * NK];         // 2.8 KB
    __shared__ uint32_t s_uh[PXB][20], s_ul[PXB][20];         // U hi/lo (k pairs)
    __shared__ uint32_t s_ch[32][20],  s_cl[32][20];          // C hi/lo

    const int tid = threadIdx.x;
    const int wid = tid >> 5;
    const int lid = tid & 31;
    const int grp = blockIdx.y;

    // ---- Stage theta (200 f4) + Li (175 f4) ----
    {
        const float4* ts = (const float4*)(theta + grp * GRP_NB * 50);
        const float4* ls = (const float4*)&g_lis;
        for (int i = tid; i < 200; i += 128) ((float4*)s_theta)[i] = ts[i];
        for (int i = tid; i < 175; i += 128) ((float4*)s_li)[i]    = ls[i];
    }
    __syncthreads();

    if (tid < 32) {
        // ---- Phase A: thread = n-row (n = 2b+axis). C[n][k] = sum_m li[m][k]*q ----
        const int b    = tid >> 1;
        const int axis = tid & 1;
        float acc[NK];
#pragma unroll
        for (int k = 0; k < NK; k++) acc[k] = 0.f;
        const float* trow = s_theta + b * 50 + axis * NCP;
#pragma unroll
        for (int m = 0; m < NCP; m++) {
            const float q = trow[m] + (axis ? cpy(m) : cpx(m));
            const float* lr = s_li + m * NK;      // lane-uniform -> broadcast
#pragma unroll
            for (int k = 0; k < NK; k++) acc[k] = fmaf(lr[k], q, acc[k]);
        }
#pragma unroll
        for (int kp = 0; kp < 14; kp++)
            hilo(acc[2*kp], acc[2*kp+1], s_ch[tid][kp], s_cl[tid][kp]);
        s_ch[tid][14] = 0; s_ch[tid][15] = 0;
        s_cl[tid][14] = 0; s_cl[tid][15] = 0;
    } else if (tid < 96) {
        // ---- U build: thread = pixel. u = d2*lg2(d2) (ln2 folded into C) ----
        const int px  = tid - 32;
        const int pid = blockIdx.x * PXB + px;
        const int h = pid / OUT_W;
        const int w = pid - h * OUT_W;
        const float gx = g_grid.g[w];
        const float gy = g_grid.g[192 + h];
        float u[NK];
#pragma unroll
        for (int n = 0; n < NCP; n++) {
            const float dx = gx - cpx(n);
            const float dy = gy - cpy(n);
            const float d2 = dx * dx + dy * dy;
            u[n] = (d2 == 0.0f) ? 0.0f : d2 * __log2f(d2);
        }
        u[25] = 1.0f; u[26] = gx; u[27] = gy;
#pragma unroll
        for (int kp = 0; kp < 14; kp++)
            hilo(u[2*kp], u[2*kp+1], s_uh[px][kp], s_ul[px][kp]);
        s_uh[px][14] = 0; s_uh[px][15] = 0;
        s_ul[px][14] = 0; s_ul[px][15] = 0;
    }
    __syncthreads();

    // ---- MMA: warp = 16 px x 32 n. 4 k-chunks x 4 n-tiles x 3 passes ----
    const int g4  = lid >> 2;     // 0..7
    const int tig = lid & 3;      // 0..3
    const int r0 = wid * 16 + g4;
    const int r1 = r0 + 8;

    uint32_t ah[8], al[8];        // [chunk*2 + {a0,a1}]
#pragma unroll
    for (int c = 0; c < 4; c++) {
        ah[2*c]   = s_uh[r0][4*c + tig];
        ah[2*c+1] = s_uh[r1][4*c + tig];
        al[2*c]   = s_ul[r0][4*c + tig];
        al[2*c+1] = s_ul[r1][4*c + tig];
    }

    const int pxbase = blockIdx.x * PXB + wid * 16;
#pragma unroll
    for (int nt = 0; nt < 4; nt++) {
        const int n = nt * 8 + g4;
        float d0 = 0.f, d1 = 0.f, d2 = 0.f, d3 = 0.f;
#pragma unroll
        for (int c = 0; c < 4; c++) {
            const uint32_t bh = s_ch[n][4*c + tig];
            const uint32_t bl = s_cl[n][4*c + tig];
            mma16n8k8(d0, d1, d2, d3, ah[2*c], ah[2*c+1], bh);   // hi*hi
            mma16n8k8(d0, d1, d2, d3, ah[2*c], ah[2*c+1], bl);   // hi*lo
            mma16n8k8(d0, d1, d2, d3, al[2*c], al[2*c+1], bh);   // lo*hi
        }
        // D: c0,c1 = (row g4, n = nt*8+2*tig, +1) -> (x,y) of batch nt*4+tig
        const int bg = grp * GRP_NB + nt * 4 + tig;
        float2* o = out + (size_t)bg * NPX + pxbase;
        o[g4]     = make_float2(d0, d1);
        o[g4 + 8] = make_float2(d2, d3);
    }
}

// ---------------------------------------------------------------------------
extern "C" void kernel_launch(void* const* d_in, const int* in_sizes, int n_in,
                              void* d_out, int out_size) {
    const float* theta = (const float*)d_in[0];
    (void)in_sizes; (void)n_in; (void)out_size;

    dim3 grid(NPX / PXB, 4);     // (768, 4)
    tps_mma_kernel<<<grid, 128>>>(theta, (float2*)d_out);
}

// round 13
// speedup vs baseline: 1.1083x; 1.1083x over previous
#include <cuda_runtime.h>
#include <cuda_fp16.h>
#include <cstdint>

// TpsGridGen: theta (64,50) -> grid (64,256,192,2) fp32
// R13: mma.sync.m16n8k8 with amortized scaffolding.
//   Block = 192 px x ALL 64 batches (N=128 n-rows). Grid = 256 blocks.
//   Phase A (coef solve) once per block, all 128 threads active.
//   Warp = 48 px x 128 n: A frags loaded once (48 regs), reused over 16
//   n-tiles; 576 HMMA/warp. fp16 hi/lo 3-pass (hi*hi+hi*lo+lo*hi), f32 accum.

#define OUT_H 256
#define OUT_W 192
#define NPX   (OUT_H * OUT_W)
#define NCP   25
#define NK    28
#define PXB   192     // pixels per block

__host__ __device__ constexpr float cpx(int n) { return 0.5f * (float)(n / 5) - 1.0f; }
__host__ __device__ constexpr float cpy(int n) { return 0.5f * (float)(n % 5) - 1.0f; }

// ---------------------------------------------------------------------------
// Compile-time inv(L), transposed to [m][k], RBF rows (k<25) pre-scaled by ln2
// ---------------------------------------------------------------------------
constexpr double cfabs(double x) { return x < 0.0 ? -x : x; }

constexpr double clog(double x) {
    int e = 0;
    while (x >= 1.4142135623730951) { x *= 0.5; e++; }
    while (x <  0.7071067811865476) { x *= 2.0; e--; }
    double t = (x - 1.0) / (x + 1.0), t2 = t * t, p = t, s = 0.0;
    for (int k = 0; k < 27; k++) { s += p / (double)(2 * k + 1); p *= t2; }
    return 2.0 * s + (double)e * 0.6931471805599453094172321214581766;
}

struct alignas(16) TPSLiS { float v[NCP][NK]; };   // [m][k]

constexpr TPSLiS make_lis() {
    const double ax[5] = {-1.0, -0.5, 0.0, 0.5, 1.0};
    double PX[NCP] = {}, PY[NCP] = {};
    for (int i = 0; i < 5; i++)
        for (int j = 0; j < 5; j++) { PX[i*5+j] = ax[i]; PY[i*5+j] = ax[j]; }

    double a[28][56] = {};
    for (int i = 0; i < 25; i++)
        for (int j = 0; j < 25; j++)
            if (i != j) {
                double dx = PX[i]-PX[j], dy = PY[i]-PY[j];
                double d2 = dx*dx + dy*dy;
                a[i][j] = d2 * clog(d2);
            }
    for (int i = 0; i < 25; i++) {
        a[i][25] = 1.0; a[i][26] = PX[i]; a[i][27] = PY[i];
        a[25][i] = 1.0; a[26][i] = PX[i]; a[27][i] = PY[i];
    }
    for (int i = 0; i < 28; i++) a[i][28+i] = 1.0;

    for (int k = 0; k < 28; k++) {
        int piv = k; double best = cfabs(a[k][k]);
        for (int i = k+1; i < 28; i++) {
            double v = cfabs(a[i][k]);
            if (v > best) { best = v; piv = i; }
        }
        if (piv != k)
            for (int j = 0; j < 56; j++) {
                double t = a[k][j]; a[k][j] = a[piv][j]; a[piv][j] = t;
            }
        double inv = 1.0 / a[k][k];
        for (int j = 0; j < 56; j++) a[k][j] *= inv;
        for (int i = 0; i < 28; i++) {
            if (i == k) continue;
            double f = a[i][k];
            if (f != 0.0)
                for (int j = 0; j < 56; j++) a[i][j] -= f * a[k][j];
        }
    }
    const double LN2 = 0.6931471805599453094172321214581766;
    TPSLiS r{};
    for (int m = 0; m < NCP; m++)
        for (int k = 0; k < NK; k++)
            r.v[m][k] = (float)(((k < 25) ? LN2 : 1.0) * a[k][28 + m]);
    return r;
}

__device__ const TPSLiS g_lis = make_lis();

// Compile-time linspace tables (numpy fp64 semantics, endpoint exact).
struct alignas(16) GridTab { float g[448]; };   // [0..191]=gx, [192..447]=gy

constexpr GridTab make_grid() {
    GridTab r{};
    for (int w = 0; w < OUT_W; w++)
        r.g[w] = (float)(-1.0 + (double)w * (2.0 / (double)(OUT_W - 1)));
    r.g[OUT_W - 1] = 1.0f;
    for (int h = 0; h < OUT_H; h++)
        r.g[192 + h] = (float)(-1.0 + (double)h * (2.0 / (double)(OUT_H - 1)));
    r.g[192 + OUT_H - 1] = 1.0f;
    return r;
}

__device__ const GridTab g_grid = make_grid();

// ---------------------------------------------------------------------------
__device__ __forceinline__ uint32_t h2bits(__half2 h) {
    return *reinterpret_cast<uint32_t*>(&h);
}

__device__ __forceinline__ void hilo(float v0, float v1, uint32_t& hi, uint32_t& lo) {
    __half2 h = __floats2half2_rn(v0, v1);
    float r0 = v0 - __low2float(h);
    float r1 = v1 - __high2float(h);
    hi = h2bits(h);
    lo = h2bits(__floats2half2_rn(r0, r1));
}

__device__ __forceinline__ void mma16n8k8(float& d0, float& d1, float& d2, float& d3,
                                          uint32_t a0, uint32_t a1, uint32_t b0) {
    asm("mma.sync.aligned.m16n8k8.row.col.f32.f16.f16.f32 "
        "{%0,%1,%2,%3},{%4,%5},{%6},{%0,%1,%2,%3};"
        : "+f"(d0), "+f"(d1), "+f"(d2), "+f"(d3)
        : "r"(a0), "r"(a1), "r"(b0));
}

// ---------------------------------------------------------------------------
// Kernel. grid 256, block 128. Block = 192 px x 64 batches (128 n-rows).
// ---------------------------------------------------------------------------
__global__ __launch_bounds__(128) void tps_mma_kernel(
    const float* __restrict__ theta, float2* __restrict__ out) {

    __shared__ __align__(16) float    s_li[NCP * NK];        // 2.8 KB
    __shared__ uint32_t s_uh[PXB][16], s_ul[PXB][16];        // 24 KB (k-pairs)
    __shared__ uint32_t s_ch[128][16], s_cl[128][16];        // 16 KB

    const int tid = threadIdx.x;
    const int wid = tid >> 5;
    const int lid = tid & 31;

    // ---- Stage Li (175 f4) ----
    {
        const float4* ls = (const float4*)&g_lis;
        for (int i = tid; i < 175; i += 128) ((float4*)s_li)[i] = ls[i];
    }
    __syncthreads();

    // ---- Phase A: thread = n-row (n = 2b+axis), theta straight from L2 ----
    {
        const int b    = tid >> 1;
        const int axis = tid & 1;
        const float* trow = theta + b * 50 + axis * NCP;
        float acc[NK];
#pragma unroll
        for (int k = 0; k < NK; k++) acc[k] = 0.f;
#pragma unroll
        for (int m = 0; m < NCP; m++) {
            const float q = trow[m] + (axis ? cpy(m) : cpx(m));
            const float* lr = s_li + m * NK;
#pragma unroll
            for (int k = 0; k < NK; k++) acc[k] = fmaf(lr[k], q, acc[k]);
        }
#pragma unroll
        for (int kp = 0; kp < 14; kp++)
            hilo(acc[2*kp], acc[2*kp+1], s_ch[tid][kp], s_cl[tid][kp]);
        s_ch[tid][14] = 0; s_ch[tid][15] = 0;
        s_cl[tid][14] = 0; s_cl[tid][15] = 0;
    }

    // ---- U build: 192 px, thread does px tid and tid+128 (if <192) ----
    for (int px = tid; px < PXB; px += 128) {
        const int pid = blockIdx.x * PXB + px;
        const int h = pid / OUT_W;
        const int w = pid - h * OUT_W;
        const float gx = g_grid.g[w];
        const float gy = g_grid.g[192 + h];
        float u[NK];
#pragma unroll
        for (int n = 0; n < NCP; n++) {
            const float dx = gx - cpx(n);
            const float dy = gy - cpy(n);
            const float d2 = dx * dx + dy * dy;
            u[n] = (d2 == 0.0f) ? 0.0f : d2 * __log2f(d2);
        }
        u[25] = 1.0f; u[26] = gx; u[27] = gy;
#pragma unroll
        for (int kp = 0; kp < 14; kp++)
            hilo(u[2*kp], u[2*kp+1], s_uh[px][kp], s_ul[px][kp]);
        s_uh[px][14] = 0; s_uh[px][15] = 0;
        s_ul[px][14] = 0; s_ul[px][15] = 0;
    }
    __syncthreads();

    // ---- MMA: warp = 48 px (3 m-tiles) x 128 n (16 n-tiles), 4 k-chunks ----
    const int g4  = lid >> 2;     // 0..7
    const int tig = lid & 3;      // 0..3

    // A fragments: loaded once, reused across all 16 n-tiles
    uint32_t ah[3][8], al[3][8];
#pragma unroll
    for (int mt = 0; mt < 3; mt++) {
        const int r0 = wid * 48 + mt * 16 + g4;
        const int r1 = r0 + 8;
#pragma unroll
        for (int c = 0; c < 4; c++) {
            ah[mt][2*c]   = s_uh[r0][4*c + tig];
            ah[mt][2*c+1] = s_uh[r1][4*c + tig];
            al[mt][2*c]   = s_ul[r0][4*c + tig];
            al[mt][2*c+1] = s_ul[r1][4*c + tig];
        }
    }

    const int pxw = blockIdx.x * PXB + wid * 48;
#pragma unroll
    for (int nt = 0; nt < 16; nt++) {
        const int n = nt * 8 + g4;
        uint32_t bh[4], bl[4];
#pragma unroll
        for (int c = 0; c < 4; c++) {
            bh[c] = s_ch[n][4*c + tig];
            bl[c] = s_cl[n][4*c + tig];
        }
        const int bg = nt * 4 + tig;          // batch
        float2* o = out + (size_t)bg * NPX + pxw;
#pragma unroll
        for (int mt = 0; mt < 3; mt++) {
            float d0 = 0.f, d1 = 0.f, d2 = 0.f, d3 = 0.f;
#pragma unroll
            for (int c = 0; c < 4; c++) {
                mma16n8k8(d0, d1, d2, d3, ah[mt][2*c], ah[mt][2*c+1], bh[c]);
                mma16n8k8(d0, d1, d2, d3, ah[mt][2*c], ah[mt][2*c+1], bl[c]);
                mma16n8k8(d0, d1, d2, d3, al[mt][2*c], al[mt][2*c+1], bh[c]);
            }
            o[mt * 16 + g4]     = make_float2(d0, d1);
            o[mt * 16 + g4 + 8] = make_float2(d2, d3);
        }
    }
}

// ---------------------------------------------------------------------------
extern "C" void kernel_launch(void* const* d_in, const int* in_sizes, int n_in,
                              void* d_out, int out_size) {
    const float* theta = (const float*)d_in[0];
    (void)in_sizes; (void)n_in; (void)out_size;

    tps_mma_kernel<<<NPX / PXB, 128>>>(theta, (float2*)d_out);
}